// round 1
// baseline (speedup 1.0000x reference)
#include <cuda_runtime.h>
#include <cstdint>
#include <cstddef>

#define NROWS 16384
#define DIN 128
#define DH 16
#define DOUT 4

// Scratch (allocations are forbidden; device globals are the sanctioned path)
__device__ float g_XW1[NROWS * DH];   // X @ W1          [16384,16]
__device__ float g_HW2[NROWS * DOUT]; // relu(...) @ W2  [16384,4]

// ---------------- PTX helpers ----------------
__device__ __forceinline__ void cp_async16(void* smem_ptr, const void* gmem_ptr) {
    unsigned saddr = (unsigned)__cvta_generic_to_shared(smem_ptr);
    asm volatile("cp.async.cg.shared.global [%0], [%1], 16;\n" :: "r"(saddr), "l"(gmem_ptr));
}
__device__ __forceinline__ void cp_commit() { asm volatile("cp.async.commit_group;\n"); }
template <int N>
__device__ __forceinline__ void cp_wait() { asm volatile("cp.async.wait_group %0;\n" :: "n"(N)); }

// packed fp32x2 FMA (ptxas will not auto-fuse; 2x FFMA throughput on sm_103a)
__device__ __forceinline__ unsigned long long dup2(float a) {
    unsigned long long r;
    asm("mov.b64 %0, {%1, %1};" : "=l"(r) : "f"(a));
    return r;
}
__device__ __forceinline__ void fma2(unsigned long long& acc, unsigned long long a, unsigned long long b) {
    asm("fma.rn.f32x2 %0, %1, %2, %0;" : "+l"(acc) : "l"(a), "l"(b));
}

// ---------------- Kernel 0: XW1 = X @ W1  [16384,128]x[128,16] ----------------
__global__ void xw1_kernel(const float* __restrict__ X, const float* __restrict__ W1,
                           float* __restrict__ XW1) {
    __shared__ float w1s[DIN * DH];
    const int tid = threadIdx.x;
    for (int i = tid; i < DIN * DH; i += 256) w1s[i] = W1[i];
    __syncthreads();

    const int row = blockIdx.x * 16 + (tid >> 4);
    const int col = tid & 15;
    const float4* xr = (const float4*)(X + (size_t)row * DIN);
    float acc = 0.0f;
#pragma unroll
    for (int k4 = 0; k4 < DIN / 4; k4++) {
        float4 x = xr[k4];
        acc += x.x * w1s[(k4 * 4 + 0) * DH + col];
        acc += x.y * w1s[(k4 * 4 + 1) * DH + col];
        acc += x.z * w1s[(k4 * 4 + 2) * DH + col];
        acc += x.w * w1s[(k4 * 4 + 3) * DH + col];
    }
    XW1[(size_t)row * DH + col] = acc;
}

// ---------------- Main streaming kernel: out-ish = A @ W (+ epilogue) ----------------
// MODE 0: T = A@W ; h = relu(T + bias) ; writes h@W2 into out  (NCOL = 16)
// MODE 1: writes A@W + bias into out                            (NCOL = 4)
template <int NCOL, int MODE>
__global__ __launch_bounds__(256, 2)
void spmm_kernel(const float* __restrict__ A, const float* __restrict__ W,
                 const float* __restrict__ bias, const float* __restrict__ W2,
                 float* __restrict__ out) {
    constexpr int BM = 64;
    constexpr int BK = 128;
    constexpr int AS_STRIDE = 132;               // pad: conflict-free LDS.128
    constexpr int NSTAGES = NROWS / BK;          // 128
    constexpr int ABUF = BM * AS_STRIDE;         // 8448 floats
    constexpr int WBUF = BK * NCOL;

    extern __shared__ float smem[];
    float* Asb[2] = { smem, smem + ABUF };
    float* Wsb[2] = { smem + 2 * ABUF, smem + 2 * ABUF + WBUF };

    const int tid  = threadIdx.x;
    const int w    = tid >> 5;      // 8 warps split K 8-ways
    const int lane = tid & 31;
    const int row0 = blockIdx.x * BM;

    auto load_stage = [&](int s) {
        const int buf = s & 1;
        const int kbase = s * BK;
#pragma unroll
        for (int t = 0; t < 8; t++) {            // 64x128 A tile: 2048 float4
            int idx = t * 256 + tid;
            int r = idx >> 5, c4 = idx & 31;
            cp_async16(Asb[buf] + r * AS_STRIDE + c4 * 4,
                       A + (size_t)(row0 + r) * NROWS + kbase + c4 * 4);
        }
        constexpr int WV = WBUF / 4;             // float4 count
#pragma unroll
        for (int t = 0; t < (WV + 255) / 256; t++) {
            int idx = t * 256 + tid;
            if (idx < WV)
                cp_async16(Wsb[buf] + idx * 4, W + (size_t)kbase * NCOL + idx * 4);
        }
        cp_commit();
    };

    load_stage(0);
    load_stage(1);

    constexpr int NP = NCOL / 2;
    unsigned long long acc0[NP];
    unsigned long long acc1[NP];
#pragma unroll
    for (int p = 0; p < NP; p++) { acc0[p] = 0ull; acc1[p] = 0ull; }

    for (int s = 0; s < NSTAGES; s++) {
        if (s + 1 < NSTAGES) cp_wait<1>(); else cp_wait<0>();
        __syncthreads();
        const int buf = s & 1;
        const float* pA0 = Asb[buf] + lane * AS_STRIDE + w * 16;
        const float* pA1 = pA0 + 32 * AS_STRIDE;
        const float* pW  = Wsb[buf] + (w * 16) * NCOL;
#pragma unroll
        for (int kk = 0; kk < 16; kk += 4) {
            float4 a0 = *(const float4*)(pA0 + kk);
            float4 a1 = *(const float4*)(pA1 + kk);
#pragma unroll
            for (int t = 0; t < 4; t++) {
                const unsigned long long* wp =
                    (const unsigned long long*)(pW + (kk + t) * NCOL);
                float a0t = (t == 0) ? a0.x : (t == 1) ? a0.y : (t == 2) ? a0.z : a0.w;
                float a1t = (t == 0) ? a1.x : (t == 1) ? a1.y : (t == 2) ? a1.z : a1.w;
                unsigned long long d0 = dup2(a0t);
                unsigned long long d1 = dup2(a1t);
#pragma unroll
                for (int p = 0; p < NP; p++) {
                    unsigned long long wv = wp[p];
                    fma2(acc0[p], d0, wv);
                    fma2(acc1[p], d1, wv);
                }
            }
        }
        __syncthreads();
        if (s + 2 < NSTAGES) load_stage(s + 2);
    }

    // ---- epilogue: reduce the 8 K-split partials ----
    __syncthreads();                    // everyone done computing; safe to alias A buffers
    float* pbuf = smem;                 // [8][BM][NCOL]  (max 32KB, fits in A region)
#pragma unroll
    for (int p = 0; p < NP; p++) {
        float2 v0 = *(float2*)&acc0[p];
        float2 v1 = *(float2*)&acc1[p];
        *(float2*)(pbuf + ((size_t)(w * BM + lane) * NCOL + 2 * p))        = v0;
        *(float2*)(pbuf + ((size_t)(w * BM + lane + 32) * NCOL + 2 * p))   = v1;
    }
    __syncthreads();

    if constexpr (MODE == 0) {
        float* hbuf = smem + 2 * ABUF;  // reuse W region: [BM][16]
        for (int i = tid; i < BM * NCOL; i += 256) {
            int r = i / NCOL, j = i % NCOL;
            float sum = 0.0f;
#pragma unroll
            for (int ww = 0; ww < 8; ww++) sum += pbuf[(size_t)(ww * BM + r) * NCOL + j];
            sum += bias[j];
            hbuf[i] = fmaxf(sum, 0.0f);
        }
        __syncthreads();
        if (tid < BM * DOUT) {
            int r = tid / DOUT, c = tid % DOUT;
            float sum = 0.0f;
#pragma unroll
            for (int j = 0; j < DH; j++) sum += hbuf[r * DH + j] * W2[j * DOUT + c];
            out[(size_t)(row0 + r) * DOUT + c] = sum;
        }
    } else {
        for (int i = tid; i < BM * NCOL; i += 256) {
            int r = i / NCOL, j = i % NCOL;
            float sum = 0.0f;
#pragma unroll
            for (int ww = 0; ww < 8; ww++) sum += pbuf[(size_t)(ww * BM + r) * NCOL + j];
            sum += bias[j];
            out[(size_t)(row0 + r) * NCOL + j] = sum;
        }
    }
}

// ---------------- launch ----------------
extern "C" void kernel_launch(void* const* d_in, const int* in_sizes, int n_in,
                              void* d_out, int out_size) {
    const float* A  = (const float*)d_in[0];  // adjacency [16384,16384]
    const float* X  = (const float*)d_in[1];  // feature   [16384,128]
    const float* W1 = (const float*)d_in[2];  // [128,16]
    const float* b1 = (const float*)d_in[3];  // [16]
    const float* W2 = (const float*)d_in[4];  // [16,4]
    const float* b2 = (const float*)d_in[5];  // [4]
    float* out = (float*)d_out;               // logits [16384,4]

    float *xw1p, *hw2p;
    cudaGetSymbolAddress((void**)&xw1p, g_XW1);
    cudaGetSymbolAddress((void**)&hw2p, g_HW2);

    // 0) XW1 = X @ W1
    xw1_kernel<<<NROWS / 16, 256>>>(X, W1, xw1p);

    // 1) HW2 = relu(A @ XW1 + b1) @ W2
    constexpr int SMEM_B = (2 * 64 * 132 + 2 * 128 * 16) * 4;   // 83968 B
    cudaFuncSetAttribute(spmm_kernel<16, 0>, cudaFuncAttributeMaxDynamicSharedMemorySize, SMEM_B);
    spmm_kernel<16, 0><<<NROWS / 64, 256, SMEM_B>>>(A, xw1p, b1, W2, hw2p);

    // 2) logits = A @ HW2 + b2
    constexpr int SMEM_C = (2 * 64 * 132 + 2 * 128 * 4) * 4;    // 71680 B
    cudaFuncSetAttribute(spmm_kernel<4, 1>, cudaFuncAttributeMaxDynamicSharedMemorySize, SMEM_C);
    spmm_kernel<4, 1><<<NROWS / 64, 256, SMEM_C>>>(A, hw2p, b2, nullptr, out);
}

// round 2
// speedup vs baseline: 1.1863x; 1.1863x over previous
#include <cuda_runtime.h>
#include <cstdint>
#include <cstddef>

#define NROWS 16384
#define DIN 128
#define DH 16
#define DOUT 4

typedef unsigned long long u64;

// Scratch (device globals: allocations are forbidden)
__device__ float g_XW1[NROWS * DH];   // X @ W1          [16384,16]
__device__ float g_HW2[NROWS * DOUT]; // relu(...) @ W2  [16384,4]

// ---------------- PTX helpers ----------------
__device__ __forceinline__ void cp_async16(void* smem_ptr, const void* gmem_ptr) {
    unsigned saddr = (unsigned)__cvta_generic_to_shared(smem_ptr);
    asm volatile("cp.async.cg.shared.global [%0], [%1], 16;\n" :: "r"(saddr), "l"(gmem_ptr));
}
__device__ __forceinline__ void cp_commit() { asm volatile("cp.async.commit_group;\n"); }
template <int N>
__device__ __forceinline__ void cp_wait() { asm volatile("cp.async.wait_group %0;\n" :: "n"(N)); }

// packed fp32x2 FMA (only reachable via PTX; 2x FFMA-3reg throughput on sm_103a)
__device__ __forceinline__ u64 dup2(float a) {
    u64 r;
    asm("mov.b64 %0, {%1, %1};" : "=l"(r) : "f"(a));
    return r;
}
__device__ __forceinline__ void fma2(u64& acc, u64 a, u64 b) {
    asm("fma.rn.f32x2 %0, %1, %2, %0;" : "+l"(acc) : "l"(a), "l"(b));
}
// zero-cost repack of an LDS.128 result into two 64-bit lanes
__device__ __forceinline__ void pack2(const float4& v, u64& lo, u64& hi) {
    asm("mov.b64 %0, {%2, %3};\n\tmov.b64 %1, {%4, %5};"
        : "=l"(lo), "=l"(hi) : "f"(v.x), "f"(v.y), "f"(v.z), "f"(v.w));
}

// ---------------- Kernel 0: XW1 = X @ W1  [16384,128]x[128,16] ----------------
__global__ __launch_bounds__(256)
void xw1_kernel(const float* __restrict__ X, const float* __restrict__ W1,
                float* __restrict__ XW1) {
    __shared__ float xs[32 * DIN];     // 16 KB
    __shared__ float w1s[DIN * DH];    // 8 KB
    const int tid = threadIdx.x;

    for (int i = tid; i < DIN * DH / 2; i += 256)
        ((float2*)w1s)[i] = ((const float2*)W1)[i];
    const float4* xg = (const float4*)(X + (size_t)blockIdx.x * 32 * DIN);
#pragma unroll
    for (int t = 0; t < 4; t++)
        ((float4*)xs)[t * 256 + tid] = xg[t * 256 + tid];
    __syncthreads();

#pragma unroll
    for (int t = 0; t < 2; t++) {
        int i = t * 256 + tid;
        int r = i >> 4, c = i & 15;
        float acc = 0.0f;
#pragma unroll
        for (int k = 0; k < DIN; k++) acc += xs[r * DIN + k] * w1s[k * DH + c];
        XW1[(size_t)(blockIdx.x * 32 + r) * DH + c] = acc;
    }
}

// ---------------- Main streaming kernel: A[16384,16384] @ W[16384,NCOL] ----------------
// MODE 0: h = relu(A@W + bias); writes h@W2 into out   (NCOL = 16)
// MODE 1: writes A@W + bias into out                    (NCOL = 4)
template <int NCOL, int MODE>
__global__ __launch_bounds__(512, 2)
void spmm_kernel(const float* __restrict__ A, const float* __restrict__ W,
                 const float* __restrict__ bias, const float* __restrict__ W2,
                 float* __restrict__ out) {
    constexpr int BM = 64;
    constexpr int BK = 128;
    constexpr int NSTAGES = NROWS / BK;      // 128
    constexpr int ABUF = BM * BK;            // 8192 floats (XOR-swizzled, no pad)
    constexpr int WBUF = BK * NCOL;
    constexpr int NP = NCOL / 2;

    extern __shared__ float smem[];
    float* As[2] = { smem, smem + ABUF };
    float* Ws[2] = { smem + 2 * ABUF, smem + 2 * ABUF + WBUF };

    const int tid  = threadIdx.x;
    const int w    = tid >> 5;               // 16 warps: (row-half, k-split-8)
    const int lane = tid & 31;
    const int ks   = (w & 7) * 16;           // this warp's k offset within a stage
    const int row  = (w >> 3) * 32 + lane;   // 0..63, unique per (w,lane)
    const int row0 = blockIdx.x * BM;

    auto load_stage = [&](int s) {
        const int buf = s & 1;
        const size_t kbase = (size_t)s * BK;
        // A tile: 64 rows x 32 chunks(16B) = 2048 chunks, 4 per thread, swizzled store
#pragma unroll
        for (int t = 0; t < 4; t++) {
            int idx = t * 512 + tid;
            int r = idx >> 5, c4 = idx & 31;
            int dst = r * 32 + (c4 ^ (r & 7));
            cp_async16(As[buf] + dst * 4,
                       A + (size_t)(row0 + r) * NROWS + kbase + c4 * 4);
        }
        constexpr int WV = WBUF / 4;          // float4 count (512 or 128)
#pragma unroll
        for (int idx = tid; idx < WV; idx += 512)
            cp_async16(Ws[buf] + idx * 4, W + kbase * NCOL + idx * 4);
        cp_commit();
    };

    load_stage(0);
    load_stage(1);

    u64 acc[NP];
#pragma unroll
    for (int p = 0; p < NP; p++) acc[p] = 0ull;

    for (int s = 0; s < NSTAGES; s++) {
        if (s + 1 < NSTAGES) cp_wait<1>(); else cp_wait<0>();
        __syncthreads();
        const int buf = s & 1;

        // A fragment: this thread's row, 16 k values = 4 swizzled LDS.128
        const float* ab = As[buf] + row * BK;
        float4 af[4];
#pragma unroll
        for (int i = 0; i < 4; i++) {
            int c4 = (ks >> 2) + i;
            af[i] = *(const float4*)(ab + ((c4 ^ (lane & 7)) << 2));
        }
        const float* wp = Ws[buf] + (size_t)ks * NCOL;
#pragma unroll
        for (int kk = 0; kk < 16; kk++) {
            float a = ((const float*)af)[kk];
            u64 ad = dup2(a);
#pragma unroll
            for (int q = 0; q < NCOL / 4; q++) {
                float4 wv = *(const float4*)(wp + kk * NCOL + q * 4);  // broadcast LDS.128
                u64 w0, w1;
                pack2(wv, w0, w1);
                fma2(acc[q * 2 + 0], ad, w0);
                fma2(acc[q * 2 + 1], ad, w1);
            }
        }
        __syncthreads();
        if (s + 2 < NSTAGES) load_stage(s + 2);
    }

    // ---- epilogue: reduce the 8 k-split partials ----
    __syncthreads();
    float* pbuf = smem;                       // [8][BM][NCOL] : 32KB (NCOL16) / 8KB (NCOL4)
    const int ksplit = w & 7;
#pragma unroll
    for (int p = 0; p < NP; p++) {
        *(float2*)(pbuf + ((size_t)(ksplit * BM + row) * NCOL + 2 * p)) = *(float2*)&acc[p];
    }
    __syncthreads();

    if constexpr (MODE == 0) {
        float* hbuf = smem + 2 * ABUF;        // [BM][16] = 4KB, reuse W region
#pragma unroll
        for (int t = 0; t < (BM * NCOL + 511) / 512; t++) {
            int i = t * 512 + tid;
            if (i < BM * NCOL) {
                int r = i / NCOL, c = i % NCOL;
                float sum = 0.0f;
#pragma unroll
                for (int sp = 0; sp < 8; sp++) sum += pbuf[(size_t)(sp * BM + r) * NCOL + c];
                sum += bias[c];
                hbuf[i] = fmaxf(sum, 0.0f);
            }
        }
        __syncthreads();
        if (tid < BM * DOUT) {
            int r = tid / DOUT, c = tid % DOUT;
            float sum = 0.0f;
#pragma unroll
            for (int j = 0; j < DH; j++) sum += hbuf[r * DH + j] * __ldg(&W2[j * DOUT + c]);
            out[(size_t)(row0 + r) * DOUT + c] = sum;
        }
    } else {
        if (tid < BM * NCOL) {
            int r = tid / NCOL, c = tid % NCOL;
            float sum = 0.0f;
#pragma unroll
            for (int sp = 0; sp < 8; sp++) sum += pbuf[(size_t)(sp * BM + r) * NCOL + c];
            sum += bias[c];
            out[(size_t)(row0 + r) * NCOL + c] = sum;
        }
    }
}

// ---------------- launch ----------------
extern "C" void kernel_launch(void* const* d_in, const int* in_sizes, int n_in,
                              void* d_out, int out_size) {
    const float* A  = (const float*)d_in[0];  // adjacency [16384,16384]
    const float* X  = (const float*)d_in[1];  // feature   [16384,128]
    const float* W1 = (const float*)d_in[2];  // [128,16]
    const float* b1 = (const float*)d_in[3];  // [16]
    const float* W2 = (const float*)d_in[4];  // [16,4]
    const float* b2 = (const float*)d_in[5];  // [4]
    float* out = (float*)d_out;               // logits [16384,4]

    float *xw1p, *hw2p;
    cudaGetSymbolAddress((void**)&xw1p, g_XW1);
    cudaGetSymbolAddress((void**)&hw2p, g_HW2);

    // 0) XW1 = X @ W1
    xw1_kernel<<<NROWS / 32, 256>>>(X, W1, xw1p);

    // 1) HW2 = relu(A @ XW1 + b1) @ W2
    constexpr int SMEM_B = (2 * 64 * 128 + 2 * 128 * 16) * 4;   // 81920 B
    cudaFuncSetAttribute(spmm_kernel<16, 0>, cudaFuncAttributeMaxDynamicSharedMemorySize, SMEM_B);
    spmm_kernel<16, 0><<<NROWS / 64, 512, SMEM_B>>>(A, xw1p, b1, W2, hw2p);

    // 2) logits = A @ HW2 + b2
    constexpr int SMEM_C = (2 * 64 * 128 + 2 * 128 * 4) * 4;    // 69632 B
    cudaFuncSetAttribute(spmm_kernel<4, 1>, cudaFuncAttributeMaxDynamicSharedMemorySize, SMEM_C);
    spmm_kernel<4, 1><<<NROWS / 64, 512, SMEM_C>>>(A, hw2p, b2, nullptr, out);
}

// round 3
// speedup vs baseline: 2.0383x; 1.7183x over previous
#include <cuda_runtime.h>
#include <cstdint>
#include <cstddef>

#define NROWS 16384
#define DIN 128
#define DH 16
#define DOUT 4

typedef unsigned long long u64;

// Scratch (device globals: allocations are forbidden)
__device__ float g_XW1[NROWS * DH];   // X @ W1          [16384,16]
__device__ float g_HW2[NROWS * DOUT]; // relu(...) @ W2  [16384,4]

// ---------------- PTX helpers ----------------
__device__ __forceinline__ void cp_async16(void* smem_ptr, const void* gmem_ptr) {
    unsigned saddr = (unsigned)__cvta_generic_to_shared(smem_ptr);
    asm volatile("cp.async.cg.shared.global [%0], [%1], 16;\n" :: "r"(saddr), "l"(gmem_ptr));
}
__device__ __forceinline__ void cp_commit() { asm volatile("cp.async.commit_group;\n"); }
template <int N>
__device__ __forceinline__ void cp_wait() { asm volatile("cp.async.wait_group %0;\n" :: "n"(N)); }

// packed fp32x2 FMA (only reachable via PTX; 2x FFMA-3reg throughput on sm_103a)
__device__ __forceinline__ u64 dup2(float a) {
    u64 r;
    asm("mov.b64 %0, {%1, %1};" : "=l"(r) : "f"(a));
    return r;
}
__device__ __forceinline__ void fma2(u64& acc, u64 a, u64 b) {
    asm("fma.rn.f32x2 %0, %1, %2, %0;" : "+l"(acc) : "l"(a), "l"(b));
}

// ---------------- Kernel 0: XW1 = X @ W1  [16384,128]x[128,16] ----------------
__global__ __launch_bounds__(256)
void xw1_kernel(const float* __restrict__ X, const float* __restrict__ W1,
                float* __restrict__ XW1) {
    __shared__ float xs[32 * DIN];     // 16 KB
    __shared__ float w1s[DIN * DH];    // 8 KB
    const int tid = threadIdx.x;

    for (int i = tid; i < DIN * DH / 2; i += 256)
        ((float2*)w1s)[i] = ((const float2*)W1)[i];
    const float4* xg = (const float4*)(X + (size_t)blockIdx.x * 32 * DIN);
#pragma unroll
    for (int t = 0; t < 4; t++)
        ((float4*)xs)[t * 256 + tid] = xg[t * 256 + tid];
    __syncthreads();

#pragma unroll
    for (int t = 0; t < 2; t++) {
        int i = t * 256 + tid;
        int r = i >> 4, c = i & 15;
        float acc = 0.0f;
#pragma unroll
        for (int k = 0; k < DIN; k++) acc += xs[r * DIN + k] * w1s[k * DH + c];
        XW1[(size_t)(blockIdx.x * 32 + r) * DH + c] = acc;
    }
}

// ---------------- Main streaming kernel: A[16384,16384] @ W[16384,NCOL] ----------------
// 256 threads: thread = (rg = tid&15, ks = tid>>4). Rows: rg + r*16 (r=0..3).
// K per stage split 16 ways, 8 k's per thread. Accumulators packed f32x2 over cols.
// MODE 0: h = relu(A@W + bias); writes h@W2 into out   (NCOL = 16)
// MODE 1: writes A@W + bias into out                    (NCOL = 4)
template <int NCOL, int MODE>
__global__ __launch_bounds__(256, 2)
void spmm_kernel(const float* __restrict__ A, const float* __restrict__ W,
                 const float* __restrict__ bias, const float* __restrict__ W2,
                 float* __restrict__ out) {
    constexpr int BM = 64;
    constexpr int BK = 128;
    constexpr int AS_STRIDE = 132;            // 16B-aligned pad
    constexpr int NSTAGES = NROWS / BK;       // 128
    constexpr int ABUF = BM * AS_STRIDE;      // 8448 floats
    constexpr int WBUF = BK * NCOL;
    constexpr int NP = NCOL / 2;              // u64 accumulators per row

    extern __shared__ float smem[];
    float* As[2] = { smem, smem + ABUF };
    float* Ws[2] = { smem + 2 * ABUF, smem + 2 * ABUF + WBUF };

    const int tid  = threadIdx.x;
    const int rg   = tid & 15;                // row group (rows rg, rg+16, rg+32, rg+48)
    const int ks   = tid >> 4;                // k split 0..15 (8 k's each)
    const int row0 = blockIdx.x * BM;

    auto load_stage = [&](int s) {
        const int buf = s & 1;
        const size_t kbase = (size_t)s * BK;
#pragma unroll
        for (int t = 0; t < 8; t++) {         // 64x128 A tile = 2048 float4
            int idx = t * 256 + tid;
            int r = idx >> 5, c4 = idx & 31;
            cp_async16(As[buf] + r * AS_STRIDE + c4 * 4,
                       A + (size_t)(row0 + r) * NROWS + kbase + c4 * 4);
        }
        constexpr int WV = WBUF / 4;          // 512 (NCOL16) or 128 (NCOL4)
#pragma unroll
        for (int t = 0; t < (WV + 255) / 256; t++) {
            int idx = t * 256 + tid;
            if (WV >= 256 || idx < WV)
                cp_async16(Ws[buf] + idx * 4, W + kbase * NCOL + idx * 4);
        }
        cp_commit();
    };

    load_stage(0);
    load_stage(1);

    u64 acc[4][NP];
#pragma unroll
    for (int r = 0; r < 4; r++)
#pragma unroll
        for (int p = 0; p < NP; p++) acc[r][p] = 0ull;

    for (int s = 0; s < NSTAGES; s++) {
        if (s + 1 < NSTAGES) cp_wait<1>(); else cp_wait<0>();
        __syncthreads();
        const int buf = s & 1;
        const float* ab = As[buf] + ks * 8;
        const float* wp = Ws[buf] + ks * 8 * NCOL;

#pragma unroll
        for (int kh = 0; kh < 2; kh++) {      // two float4 halves of the 8-k chunk
            float4 af[4];
#pragma unroll
            for (int r = 0; r < 4; r++)
                af[r] = *(const float4*)(ab + (rg + r * 16) * AS_STRIDE + kh * 4);
#pragma unroll
            for (int k2 = 0; k2 < 4; k2++) {
                const int k = kh * 4 + k2;
                u64 ad[4];
#pragma unroll
                for (int r = 0; r < 4; r++)
                    ad[r] = dup2(((const float*)&af[r])[k2]);
                const ulonglong2* wrow = (const ulonglong2*)(wp + k * NCOL);
#pragma unroll
                for (int q = 0; q < NCOL / 4; q++) {
                    ulonglong2 w2 = wrow[q];  // LDS.128, pre-paired for f32x2
#pragma unroll
                    for (int r = 0; r < 4; r++) {
                        fma2(acc[r][2 * q + 0], ad[r], w2.x);
                        fma2(acc[r][2 * q + 1], ad[r], w2.y);
                    }
                }
            }
        }
        __syncthreads();
        if (s + 2 < NSTAGES) load_stage(s + 2);
    }

    // ---- epilogue: reduce the 16 k-split partials ----
    float* pbuf = smem;                       // [16][BM][NCOL]: 64KB (NCOL16) / 16KB (NCOL4)
#pragma unroll
    for (int r = 0; r < 4; r++)
#pragma unroll
        for (int p = 0; p < NP; p++)
            *(float2*)(pbuf + ((size_t)(ks * BM + rg + r * 16) * NCOL + 2 * p)) =
                *(float2*)&acc[r][p];
    __syncthreads();

    if constexpr (MODE == 0) {
        float* hbuf = smem + 2 * ABUF;        // [BM][16] = 4KB in W region
#pragma unroll
        for (int t = 0; t < 4; t++) {
            int i = t * 256 + tid;            // 1024 items
            int r = i / NCOL, c = i % NCOL;
            float sum = 0.0f;
#pragma unroll
            for (int sp = 0; sp < 16; sp++) sum += pbuf[(size_t)(sp * BM + r) * NCOL + c];
            sum += __ldg(&bias[c]);
            hbuf[i] = fmaxf(sum, 0.0f);
        }
        __syncthreads();
        {
            int r = tid / DOUT, c = tid % DOUT;   // 256 outputs
            float sum = 0.0f;
#pragma unroll
            for (int j = 0; j < DH; j++) sum += hbuf[r * DH + j] * __ldg(&W2[j * DOUT + c]);
            out[(size_t)(row0 + r) * DOUT + c] = sum;
        }
    } else {
        int r = tid / NCOL, c = tid % NCOL;       // 256 outputs
        float sum = 0.0f;
#pragma unroll
        for (int sp = 0; sp < 16; sp++) sum += pbuf[(size_t)(sp * BM + r) * NCOL + c];
        sum += __ldg(&bias[c]);
        out[(size_t)(row0 + r) * NCOL + c] = sum;
    }
}

// ---------------- launch ----------------
extern "C" void kernel_launch(void* const* d_in, const int* in_sizes, int n_in,
                              void* d_out, int out_size) {
    const float* A  = (const float*)d_in[0];  // adjacency [16384,16384]
    const float* X  = (const float*)d_in[1];  // feature   [16384,128]
    const float* W1 = (const float*)d_in[2];  // [128,16]
    const float* b1 = (const float*)d_in[3];  // [16]
    const float* W2 = (const float*)d_in[4];  // [16,4]
    const float* b2 = (const float*)d_in[5];  // [4]
    float* out = (float*)d_out;               // logits [16384,4]

    float *xw1p, *hw2p;
    cudaGetSymbolAddress((void**)&xw1p, g_XW1);
    cudaGetSymbolAddress((void**)&hw2p, g_HW2);

    // 0) XW1 = X @ W1
    xw1_kernel<<<NROWS / 32, 256>>>(X, W1, xw1p);

    // 1) HW2 = relu(A @ XW1 + b1) @ W2
    constexpr int SMEM_B = (2 * 64 * 132 + 2 * 128 * 16) * 4;   // 83968 B
    cudaFuncSetAttribute(spmm_kernel<16, 0>, cudaFuncAttributeMaxDynamicSharedMemorySize, SMEM_B);
    spmm_kernel<16, 0><<<NROWS / 64, 256, SMEM_B>>>(A, xw1p, b1, W2, hw2p);

    // 2) logits = A @ HW2 + b2
    constexpr int SMEM_C = (2 * 64 * 132 + 2 * 128 * 4) * 4;    // 71680 B
    cudaFuncSetAttribute(spmm_kernel<4, 1>, cudaFuncAttributeMaxDynamicSharedMemorySize, SMEM_C);
    spmm_kernel<4, 1><<<NROWS / 64, 256, SMEM_C>>>(A, hw2p, b2, nullptr, out);
}

// round 6
// speedup vs baseline: 2.0946x; 1.0276x over previous
#include <cuda_runtime.h>
#include <cstdint>
#include <cstddef>

#define NROWS 16384
#define DIN 128
#define DH 16
#define DOUT 4

typedef unsigned long long u64;
typedef unsigned int u32;

// Scratch (device globals: allocations are forbidden)
__device__ float g_WT[2 * DH * NROWS]; // rows 0-15: tf32_hi((X@W1)^T), rows 16-31: tf32_lo
__device__ float g_HW2[NROWS * DOUT];  // relu(...) @ W2  [16384,4]

// ---------------- PTX helpers ----------------
__device__ __forceinline__ void cp_async16(void* smem_ptr, const void* gmem_ptr) {
    unsigned saddr = (unsigned)__cvta_generic_to_shared(smem_ptr);
    asm volatile("cp.async.cg.shared.global [%0], [%1], 16;\n" :: "r"(saddr), "l"(gmem_ptr));
}
__device__ __forceinline__ void cp_commit() { asm volatile("cp.async.commit_group;\n"); }
template <int N>
__device__ __forceinline__ void cp_wait() { asm volatile("cp.async.wait_group %0;\n" :: "n"(N)); }

__device__ __forceinline__ u64 dup2(float a) {
    u64 r; asm("mov.b64 %0, {%1, %1};" : "=l"(r) : "f"(a)); return r;
}
__device__ __forceinline__ void fma2(u64& acc, u64 a, u64 b) {
    asm("fma.rn.f32x2 %0, %1, %2, %0;" : "+l"(acc) : "l"(a), "l"(b));
}
__device__ __forceinline__ u32 cvt_tf32(float x) {
    u32 r; asm("cvt.rna.tf32.f32 %0, %1;" : "=r"(r) : "f"(x)); return r;
}
// m16n8k8 tf32 HMMA (base sm_80+ ISA, valid on non-'a' sm_103 target)
__device__ __forceinline__ void mma_tf32(float4& d, u32 a0, u32 a1, u32 a2, u32 a3,
                                         u32 b0, u32 b1) {
    asm volatile("mma.sync.aligned.m16n8k8.row.col.f32.tf32.tf32.f32 "
                 "{%0,%1,%2,%3}, {%4,%5,%6,%7}, {%8,%9}, {%0,%1,%2,%3};"
                 : "+f"(d.x), "+f"(d.y), "+f"(d.z), "+f"(d.w)
                 : "r"(a0), "r"(a1), "r"(a2), "r"(a3), "r"(b0), "r"(b1));
}

// ---------------- Kernel 0: WT_hi/lo = tf32-split of (X @ W1)^T ----------------
__global__ __launch_bounds__(256)
void xw1t_kernel(const float* __restrict__ X, const float* __restrict__ W1,
                 float* __restrict__ WT) {
    __shared__ float xs[32 * DIN];
    __shared__ float w1s[DIN * DH];
    const int tid = threadIdx.x;
    for (int i = tid; i < DIN * DH / 2; i += 256)
        ((float2*)w1s)[i] = ((const float2*)W1)[i];
    const float4* xg = (const float4*)(X + (size_t)blockIdx.x * 32 * DIN);
#pragma unroll
    for (int t = 0; t < 4; t++)
        ((float4*)xs)[t * 256 + tid] = xg[t * 256 + tid];
    __syncthreads();
#pragma unroll
    for (int t = 0; t < 2; t++) {
        int i = t * 256 + tid;
        int r = i >> 4, c = i & 15;
        float acc = 0.0f;
#pragma unroll
        for (int k = 0; k < DIN; k++) acc += xs[r * DIN + k] * w1s[k * DH + c];
        u32 hi = cvt_tf32(acc);
        float lo = acc - __uint_as_float(hi);
        size_t col = (size_t)blockIdx.x * 32 + r;
        WT[(size_t)c * NROWS + col]              = __uint_as_float(hi);
        WT[(size_t)(DH + c) * NROWS + col]       = __uint_as_float(cvt_tf32(lo));
    }
}

// ---------------- Pass 1 (HMMA 3xTF32): HW2 = relu(A @ XW1 + b1) @ W2 ----------------
// 256 threads, 8 warps = (rowgroup rg=w&3) x (k-half kh=w>>2).
// Warp accumulates C[16x16] over 128 K-stages via mma.sync m16n8k8 with tf32 split.
__global__ __launch_bounds__(256, 2)
void pass1_mma(const float* __restrict__ A, const float* __restrict__ WT,
               const float* __restrict__ b1, const float* __restrict__ W2,
               float* __restrict__ out) {
    constexpr int BM = 64, BK = 128;
    constexpr int STRIDE = 132;
    constexpr int NST = NROWS / BK;           // 128
    constexpr int ABUF = BM * STRIDE;         // 8448 floats
    constexpr int WBUF = DH * STRIDE;         // 2112 floats (one of hi/lo)
    constexpr int SB = ABUF + 2 * WBUF;       // 12672 floats per stage

    extern __shared__ float fsm[];
    const int tid  = threadIdx.x;
    const int w    = tid >> 5;
    const int lane = tid & 31;
    const int gid  = lane >> 2;
    const int tig  = lane & 3;
    const int rg   = w & 3;
    const int kh   = w >> 2;
    const int row0 = blockIdx.x * BM;

    auto load_stage = [&](int s) {
        float* base = fsm + (s & 1) * SB;
        const size_t kb = (size_t)s * BK;
#pragma unroll
        for (int t = 0; t < 8; t++) {          // A: 64x128 = 2048 float4
            int idx = t * 256 + tid;
            int r = idx >> 5, c4 = idx & 31;
            cp_async16(base + r * STRIDE + c4 * 4,
                       A + (size_t)(row0 + r) * NROWS + kb + c4 * 4);
        }
#pragma unroll
        for (int t = 0; t < 4; t++) {          // WT hi+lo: 32 rows x 32 chunks = 1024 float4
            int idx = t * 256 + tid;
            int r = idx >> 5, c4 = idx & 31;   // r: 0-15 hi, 16-31 lo
            cp_async16(base + ABUF + r * STRIDE + c4 * 4,
                       WT + (size_t)r * NROWS + kb + c4 * 4);
        }
        cp_commit();
    };

    load_stage(0);
    load_stage(1);

    float4 C0 = make_float4(0.f, 0.f, 0.f, 0.f);
    float4 C1 = make_float4(0.f, 0.f, 0.f, 0.f);

    for (int s = 0; s < NST; s++) {
        if (s + 1 < NST) cp_wait<1>(); else cp_wait<0>();
        __syncthreads();
        const float* base = fsm + (s & 1) * SB;
        const float* ap = base + (rg * 16 + gid) * STRIDE + kh * 64 + tig;
        const float* bh = base + ABUF + gid * STRIDE + kh * 64 + tig;
        const float* bl = bh + DH * STRIDE;    // lo rows live 16 rows further
#pragma unroll
        for (int k8 = 0; k8 < 8; k8++) {
            // A values + tf32 split
            float av0 = ap[0], av1 = ap[8 * STRIDE], av2 = ap[4], av3 = ap[8 * STRIDE + 4];
            u32 ah0 = cvt_tf32(av0), ah1 = cvt_tf32(av1), ah2 = cvt_tf32(av2), ah3 = cvt_tf32(av3);
            u32 al0 = cvt_tf32(av0 - __uint_as_float(ah0));
            u32 al1 = cvt_tf32(av1 - __uint_as_float(ah1));
            u32 al2 = cvt_tf32(av2 - __uint_as_float(ah2));
            u32 al3 = cvt_tf32(av3 - __uint_as_float(ah3));
            // B fragments: hi/lo already tf32 bit patterns
            u32 bh00 = __float_as_uint(bh[0]);
            u32 bh01 = __float_as_uint(bh[4]);
            u32 bh10 = __float_as_uint(bh[8 * STRIDE]);
            u32 bh11 = __float_as_uint(bh[8 * STRIDE + 4]);
            u32 bl00 = __float_as_uint(bl[0]);
            u32 bl01 = __float_as_uint(bl[4]);
            u32 bl10 = __float_as_uint(bl[8 * STRIDE]);
            u32 bl11 = __float_as_uint(bl[8 * STRIDE + 4]);
            // 3xTF32: hi*hi + lo*hi + hi*lo
            mma_tf32(C0, ah0, ah1, ah2, ah3, bh00, bh01);
            mma_tf32(C0, al0, al1, al2, al3, bh00, bh01);
            mma_tf32(C0, ah0, ah1, ah2, ah3, bl00, bl01);
            mma_tf32(C1, ah0, ah1, ah2, ah3, bh10, bh11);
            mma_tf32(C1, al0, al1, al2, al3, bh10, bh11);
            mma_tf32(C1, ah0, ah1, ah2, ah3, bl10, bl11);
            ap += 8; bh += 8; bl += 8;
        }
        __syncthreads();
        if (s + 2 < NST) load_stage(s + 2);
    }

    // ---- epilogue: combine two k-halves, bias+relu, fuse H@W2 ----
    float* psum = fsm;                         // [2][64][16] = 8 KB
    {
        const int rowb = rg * 16 + gid;
        float* p = psum + kh * (BM * DH);
        *(float2*)(p + rowb * DH + 2 * tig)           = make_float2(C0.x, C0.y);
        *(float2*)(p + (rowb + 8) * DH + 2 * tig)     = make_float2(C0.z, C0.w);
        *(float2*)(p + rowb * DH + 8 + 2 * tig)       = make_float2(C1.x, C1.y);
        *(float2*)(p + (rowb + 8) * DH + 8 + 2 * tig) = make_float2(C1.z, C1.w);
    }
    __syncthreads();
    {
        const int r = tid >> 2, c = tid & 3;
        float o = 0.0f;
#pragma unroll
        for (int j = 0; j < DH; j++) {
            float h = psum[r * DH + j] + psum[BM * DH + r * DH + j] + __ldg(&b1[j]);
            h = fmaxf(h, 0.0f);
            o += h * __ldg(&W2[j * DOUT + c]);
        }
        out[(size_t)(row0 + r) * DOUT + c] = o;
    }
}

// ---------------- Pass 2 (SIMT, memory-bound): logits = A @ HW2 + b2 ----------------
__global__ __launch_bounds__(256, 2)
void pass2_kernel(const float* __restrict__ A, const float* __restrict__ W,
                  const float* __restrict__ bias, float* __restrict__ out) {
    constexpr int NCOL = 4;
    constexpr int BM = 64, BK = 128;
    constexpr int AS_STRIDE = 132;
    constexpr int NSTAGES = NROWS / BK;
    constexpr int ABUF = BM * AS_STRIDE;
    constexpr int WBUF = BK * NCOL;
    constexpr int NP = NCOL / 2;

    extern __shared__ float fsm[];
    float* As[2] = { fsm, fsm + ABUF };
    float* Ws[2] = { fsm + 2 * ABUF, fsm + 2 * ABUF + WBUF };

    const int tid = threadIdx.x;
    const int rg = tid & 15;
    const int ks = tid >> 4;
    const int row0 = blockIdx.x * BM;

    auto load_stage = [&](int s) {
        const int buf = s & 1;
        const size_t kbase = (size_t)s * BK;
#pragma unroll
        for (int t = 0; t < 8; t++) {
            int idx = t * 256 + tid;
            int r = idx >> 5, c4 = idx & 31;
            cp_async16(As[buf] + r * AS_STRIDE + c4 * 4,
                       A + (size_t)(row0 + r) * NROWS + kbase + c4 * 4);
        }
        if (tid < WBUF / 4)
            cp_async16(Ws[buf] + tid * 4, W + kbase * NCOL + tid * 4);
        cp_commit();
    };

    load_stage(0);
    load_stage(1);

    u64 acc[4][NP];
#pragma unroll
    for (int r = 0; r < 4; r++)
#pragma unroll
        for (int p = 0; p < NP; p++) acc[r][p] = 0ull;

    for (int s = 0; s < NSTAGES; s++) {
        if (s + 1 < NSTAGES) cp_wait<1>(); else cp_wait<0>();
        __syncthreads();
        const int buf = s & 1;
        const float* ab = As[buf] + ks * 8;
        const float* wp = Ws[buf] + ks * 8 * NCOL;
#pragma unroll
        for (int kh = 0; kh < 2; kh++) {
            float4 af[4];
#pragma unroll
            for (int r = 0; r < 4; r++)
                af[r] = *(const float4*)(ab + (rg + r * 16) * AS_STRIDE + kh * 4);
#pragma unroll
            for (int k2 = 0; k2 < 4; k2++) {
                const int k = kh * 4 + k2;
                u64 ad[4];
#pragma unroll
                for (int r = 0; r < 4; r++)
                    ad[r] = dup2(((const float*)&af[r])[k2]);
                const ulonglong2* wrow = (const ulonglong2*)(wp + k * NCOL);
                ulonglong2 w2v = wrow[0];
#pragma unroll
                for (int r = 0; r < 4; r++) {
                    fma2(acc[r][0], ad[r], w2v.x);
                    fma2(acc[r][1], ad[r], w2v.y);
                }
            }
        }
        __syncthreads();
        if (s + 2 < NSTAGES) load_stage(s + 2);
    }

    float* pbuf = fsm;                 // [16][BM][4] = 16KB
#pragma unroll
    for (int r = 0; r < 4; r++)
#pragma unroll
        for (int p = 0; p < NP; p++)
            *(float2*)(pbuf + ((size_t)(ks * BM + rg + r * 16) * NCOL + 2 * p)) =
                *(float2*)&acc[r][p];
    __syncthreads();

    int r = tid / NCOL, c = tid % NCOL;
    float sum = 0.0f;
#pragma unroll
    for (int sp = 0; sp < 16; sp++) sum += pbuf[(size_t)(sp * BM + r) * NCOL + c];
    sum += __ldg(&bias[c]);
    out[(size_t)(row0 + r) * NCOL + c] = sum;
}

// ---------------- launch ----------------
extern "C" void kernel_launch(void* const* d_in, const int* in_sizes, int n_in,
                              void* d_out, int out_size) {
    const float* A  = (const float*)d_in[0];
    const float* X  = (const float*)d_in[1];
    const float* W1 = (const float*)d_in[2];
    const float* b1 = (const float*)d_in[3];
    const float* W2 = (const float*)d_in[4];
    const float* b2 = (const float*)d_in[5];
    float* out = (float*)d_out;

    float *wtp, *hw2p;
    cudaGetSymbolAddress((void**)&wtp, g_WT);
    cudaGetSymbolAddress((void**)&hw2p, g_HW2);

    // 0) WT = tf32-split (X @ W1)^T
    xw1t_kernel<<<NROWS / 32, 256>>>(X, W1, wtp);

    // 1) HW2 = relu(A @ XW1 + b1) @ W2   (mma.sync 3xTF32)
    constexpr int SMEM_P1 = 2 * (64 * 132 + 2 * 16 * 132) * 4;   // 101376 B
    cudaFuncSetAttribute(pass1_mma, cudaFuncAttributeMaxDynamicSharedMemorySize, SMEM_P1);
    pass1_mma<<<NROWS / 64, 256, SMEM_P1>>>(A, wtp, b1, W2, hw2p);

    // 2) logits = A @ HW2 + b2           (SIMT, memory-bound)
    constexpr int SMEM_P2 = (2 * 64 * 132 + 2 * 128 * 4) * 4;    // 71680 B
    cudaFuncSetAttribute(pass2_kernel, cudaFuncAttributeMaxDynamicSharedMemorySize, SMEM_P2);
    pass2_kernel<<<NROWS / 64, 256, SMEM_P2>>>(A, hw2p, b2, out);
}

// round 7
// speedup vs baseline: 2.0974x; 1.0013x over previous
#include <cuda_runtime.h>
#include <cstdint>
#include <cstddef>

#define NROWS 16384
#define DIN 128
#define DH 16
#define DOUT 4

typedef unsigned long long u64;
typedef unsigned int u32;

// Scratch (device globals: allocations are forbidden)
__device__ float g_WT[2 * DH * NROWS]; // rows 0-15: tf32_hi((X@W1)^T), rows 16-31: tf32_lo
__device__ float g_HW2[NROWS * DOUT];  // relu(...) @ W2  [16384,4]

// ---------------- PTX helpers ----------------
__device__ __forceinline__ void cp_async16(void* smem_ptr, const void* gmem_ptr) {
    unsigned saddr = (unsigned)__cvta_generic_to_shared(smem_ptr);
    asm volatile("cp.async.cg.shared.global [%0], [%1], 16;\n" :: "r"(saddr), "l"(gmem_ptr));
}
__device__ __forceinline__ void cp_commit() { asm volatile("cp.async.commit_group;\n"); }
template <int N>
__device__ __forceinline__ void cp_wait() { asm volatile("cp.async.wait_group %0;\n" :: "n"(N)); }

__device__ __forceinline__ u64 dup2(float a) {
    u64 r; asm("mov.b64 %0, {%1, %1};" : "=l"(r) : "f"(a)); return r;
}
__device__ __forceinline__ void fma2(u64& acc, u64 a, u64 b) {
    asm("fma.rn.f32x2 %0, %1, %2, %0;" : "+l"(acc) : "l"(a), "l"(b));
}
__device__ __forceinline__ u32 cvt_tf32(float x) {
    u32 r; asm("cvt.rna.tf32.f32 %0, %1;" : "=r"(r) : "f"(x)); return r;
}
// m16n8k8 tf32 HMMA (base sm_80+ ISA, valid on non-'a' sm_103 target)
__device__ __forceinline__ void mma_tf32(float4& d, u32 a0, u32 a1, u32 a2, u32 a3,
                                         u32 b0, u32 b1) {
    asm volatile("mma.sync.aligned.m16n8k8.row.col.f32.tf32.tf32.f32 "
                 "{%0,%1,%2,%3}, {%4,%5,%6,%7}, {%8,%9}, {%0,%1,%2,%3};"
                 : "+f"(d.x), "+f"(d.y), "+f"(d.z), "+f"(d.w)
                 : "r"(a0), "r"(a1), "r"(a2), "r"(a3), "r"(b0), "r"(b1));
}

// ---------------- Kernel 0: WT_hi/lo = tf32-split of (X @ W1)^T ----------------
__global__ __launch_bounds__(256)
void xw1t_kernel(const float* __restrict__ X, const float* __restrict__ W1,
                 float* __restrict__ WT) {
    __shared__ float xs[32 * DIN];
    __shared__ float w1s[DIN * DH];
    const int tid = threadIdx.x;
    for (int i = tid; i < DIN * DH / 2; i += 256)
        ((float2*)w1s)[i] = ((const float2*)W1)[i];
    const float4* xg = (const float4*)(X + (size_t)blockIdx.x * 32 * DIN);
#pragma unroll
    for (int t = 0; t < 4; t++)
        ((float4*)xs)[t * 256 + tid] = xg[t * 256 + tid];
    __syncthreads();
#pragma unroll
    for (int t = 0; t < 2; t++) {
        int i = t * 256 + tid;
        int r = i >> 4, c = i & 15;
        float acc = 0.0f;
#pragma unroll
        for (int k = 0; k < DIN; k++) acc += xs[r * DIN + k] * w1s[k * DH + c];
        u32 hi = cvt_tf32(acc);
        float lo = acc - __uint_as_float(hi);
        size_t col = (size_t)blockIdx.x * 32 + r;
        WT[(size_t)c * NROWS + col]        = __uint_as_float(hi);
        WT[(size_t)(DH + c) * NROWS + col] = __uint_as_float(cvt_tf32(lo));
    }
}

// ---------------- Pass 1 (HMMA 3xTF32): HW2 = relu(A @ XW1 + b1) @ W2 ----------------
// 8 warps = pure k-split (warp w owns k in [16w,16w+16) per stage), each warp
// computes ALL 4 m16-tiles x n16 so B fragments are loaded once, not 4x.
__global__ __launch_bounds__(256, 2)
void pass1_mma(const float* __restrict__ A, const float* __restrict__ WT,
               const float* __restrict__ b1, const float* __restrict__ W2,
               float* __restrict__ out) {
    constexpr int BM = 64, BK = 128;
    constexpr int STRIDE = 132;
    constexpr int NST = NROWS / BK;           // 128
    constexpr int ABUF = BM * STRIDE;         // 8448 floats
    constexpr int WBUF = DH * STRIDE;         // 2112 floats (hi or lo block)
    constexpr int SB = ABUF + 2 * WBUF;       // 12672 floats per stage

    extern __shared__ float fsm[];
    const int tid  = threadIdx.x;
    const int w    = tid >> 5;                // ksplit 0..7
    const int lane = tid & 31;
    const int gid  = lane >> 2;               // 0..7
    const int tig  = lane & 3;                // 0..3
    const int row0 = blockIdx.x * BM;

    auto load_stage = [&](int s) {
        float* base = fsm + (s & 1) * SB;
        const size_t kb = (size_t)s * BK;
#pragma unroll
        for (int t = 0; t < 8; t++) {          // A: 64x128 = 2048 float4
            int idx = t * 256 + tid;
            int r = idx >> 5, c4 = idx & 31;
            cp_async16(base + r * STRIDE + c4 * 4,
                       A + (size_t)(row0 + r) * NROWS + kb + c4 * 4);
        }
#pragma unroll
        for (int t = 0; t < 4; t++) {          // WT hi+lo: 32 rows x 32 chunks
            int idx = t * 256 + tid;
            int r = idx >> 5, c4 = idx & 31;
            cp_async16(base + ABUF + r * STRIDE + c4 * 4,
                       WT + (size_t)r * NROWS + kb + c4 * 4);
        }
        cp_commit();
    };

    load_stage(0);
    load_stage(1);

    float4 C[4][2];                            // [mtile][ntile]
#pragma unroll
    for (int m = 0; m < 4; m++)
#pragma unroll
        for (int n = 0; n < 2; n++) C[m][n] = make_float4(0.f, 0.f, 0.f, 0.f);

    for (int s = 0; s < NST; s++) {
        if (s + 1 < NST) cp_wait<1>(); else cp_wait<0>();
        __syncthreads();
        const float* base = fsm + (s & 1) * SB;
        const int k0 = w * 16;
#pragma unroll
        for (int k8 = 0; k8 < 2; k8++) {
            const float* bh = base + ABUF + gid * STRIDE + k0 + k8 * 8 + tig;
            const float* bl = bh + DH * STRIDE;
            u32 bh00 = __float_as_uint(bh[0]);
            u32 bh01 = __float_as_uint(bh[4]);
            u32 bh10 = __float_as_uint(bh[8 * STRIDE]);
            u32 bh11 = __float_as_uint(bh[8 * STRIDE + 4]);
            u32 bl00 = __float_as_uint(bl[0]);
            u32 bl01 = __float_as_uint(bl[4]);
            u32 bl10 = __float_as_uint(bl[8 * STRIDE]);
            u32 bl11 = __float_as_uint(bl[8 * STRIDE + 4]);
#pragma unroll
            for (int mt = 0; mt < 4; mt++) {
                const float* ap = base + (mt * 16 + gid) * STRIDE + k0 + k8 * 8 + tig;
                float av0 = ap[0], av1 = ap[8 * STRIDE], av2 = ap[4], av3 = ap[8 * STRIDE + 4];
                u32 ah0 = cvt_tf32(av0), ah1 = cvt_tf32(av1);
                u32 ah2 = cvt_tf32(av2), ah3 = cvt_tf32(av3);
                u32 al0 = cvt_tf32(av0 - __uint_as_float(ah0));
                u32 al1 = cvt_tf32(av1 - __uint_as_float(ah1));
                u32 al2 = cvt_tf32(av2 - __uint_as_float(ah2));
                u32 al3 = cvt_tf32(av3 - __uint_as_float(ah3));
                mma_tf32(C[mt][0], ah0, ah1, ah2, ah3, bh00, bh01);
                mma_tf32(C[mt][0], al0, al1, al2, al3, bh00, bh01);
                mma_tf32(C[mt][0], ah0, ah1, ah2, ah3, bl00, bl01);
                mma_tf32(C[mt][1], ah0, ah1, ah2, ah3, bh10, bh11);
                mma_tf32(C[mt][1], al0, al1, al2, al3, bh10, bh11);
                mma_tf32(C[mt][1], ah0, ah1, ah2, ah3, bl10, bl11);
            }
        }
        __syncthreads();
        if (s + 2 < NST) load_stage(s + 2);
    }

    // ---- epilogue: reduce 8 ksplit partials, bias+relu, fuse H@W2 ----
    float* psum = fsm;                         // [8][64][16] = 32 KB
    {
        float* p = psum + w * (BM * DH);
#pragma unroll
        for (int mt = 0; mt < 4; mt++) {
            const int rb = mt * 16 + gid;
            *(float2*)(p + rb * DH + 2 * tig)           = make_float2(C[mt][0].x, C[mt][0].y);
            *(float2*)(p + (rb + 8) * DH + 2 * tig)     = make_float2(C[mt][0].z, C[mt][0].w);
            *(float2*)(p + rb * DH + 8 + 2 * tig)       = make_float2(C[mt][1].x, C[mt][1].y);
            *(float2*)(p + (rb + 8) * DH + 8 + 2 * tig) = make_float2(C[mt][1].z, C[mt][1].w);
        }
    }
    __syncthreads();
    float* hbuf = fsm + 8 * BM * DH;           // [64][16] right after psum
#pragma unroll
    for (int t = 0; t < 4; t++) {
        int i = t * 256 + tid;                 // 1024 h values
        float sum = 0.0f;
#pragma unroll
        for (int sp = 0; sp < 8; sp++) sum += psum[sp * (BM * DH) + i];
        sum += __ldg(&b1[i & 15]);
        hbuf[i] = fmaxf(sum, 0.0f);
    }
    __syncthreads();
    {
        const int r = tid >> 2, c = tid & 3;
        float o = 0.0f;
#pragma unroll
        for (int j = 0; j < DH; j++)
            o += hbuf[r * DH + j] * __ldg(&W2[j * DOUT + c]);
        out[(size_t)(row0 + r) * DOUT + c] = o;
    }
}

// ---------------- Pass 2 (SIMT, memory-bound): logits = A @ HW2 + b2 ----------------
// 8 warps = ksplit (16 k's each); thread owns rows (lane, lane+32).
// A LDS.128 conflict-free (consecutive rows); W loads warp-uniform broadcasts.
__global__ __launch_bounds__(256, 2)
void pass2_kernel(const float* __restrict__ A, const float* __restrict__ W,
                  const float* __restrict__ bias, float* __restrict__ out) {
    constexpr int NCOL = 4;
    constexpr int BM = 64, BK = 128;
    constexpr int STRIDE = 132;
    constexpr int NST = NROWS / BK;
    constexpr int ABUF = BM * STRIDE;
    constexpr int WBUF = BK * NCOL;

    extern __shared__ float fsm[];
    float* As[2] = { fsm, fsm + ABUF };
    float* Ws[2] = { fsm + 2 * ABUF, fsm + 2 * ABUF + WBUF };

    const int tid  = threadIdx.x;
    const int w    = tid >> 5;                // ksplit 0..7 (16 k's)
    const int lane = tid & 31;
    const int row0 = blockIdx.x * BM;

    auto load_stage = [&](int s) {
        const int buf = s & 1;
        const size_t kbase = (size_t)s * BK;
#pragma unroll
        for (int t = 0; t < 8; t++) {
            int idx = t * 256 + tid;
            int r = idx >> 5, c4 = idx & 31;
            cp_async16(As[buf] + r * STRIDE + c4 * 4,
                       A + (size_t)(row0 + r) * NROWS + kbase + c4 * 4);
        }
        if (tid < WBUF / 4)
            cp_async16(Ws[buf] + tid * 4, W + kbase * NCOL + tid * 4);
        cp_commit();
    };

    load_stage(0);
    load_stage(1);

    u64 acc[2][2] = {{0ull, 0ull}, {0ull, 0ull}};   // [rowhalf][colpair]

    for (int s = 0; s < NST; s++) {
        if (s + 1 < NST) cp_wait<1>(); else cp_wait<0>();
        __syncthreads();
        const int buf = s & 1;
        const float* ab = As[buf] + lane * STRIDE + w * 16;
        const float* wp = Ws[buf] + w * 16 * NCOL;
#pragma unroll
        for (int kh = 0; kh < 4; kh++) {               // 4 x float4 per row half
            float4 a0 = *(const float4*)(ab + kh * 4);
            float4 a1 = *(const float4*)(ab + 32 * STRIDE + kh * 4);
#pragma unroll
            for (int k2 = 0; k2 < 4; k2++) {
                const int k = kh * 4 + k2;
                ulonglong2 wv = *(const ulonglong2*)(wp + k * NCOL);  // warp-uniform
                u64 d0 = dup2(((const float*)&a0)[k2]);
                u64 d1 = dup2(((const float*)&a1)[k2]);
                fma2(acc[0][0], d0, wv.x);
                fma2(acc[0][1], d0, wv.y);
                fma2(acc[1][0], d1, wv.x);
                fma2(acc[1][1], d1, wv.y);
            }
        }
        __syncthreads();
        if (s + 2 < NST) load_stage(s + 2);
    }

    // ---- epilogue: reduce 8 ksplit partials ----
    float* pbuf = fsm;                         // [8][64][4] = 8 KB
#pragma unroll
    for (int rh = 0; rh < 2; rh++)
        *(float4*)(pbuf + (size_t)(w * BM + lane + rh * 32) * NCOL) =
            make_float4(__uint_as_float((u32)acc[rh][0]),
                        __uint_as_float((u32)(acc[rh][0] >> 32)),
                        __uint_as_float((u32)acc[rh][1]),
                        __uint_as_float((u32)(acc[rh][1] >> 32)));
    __syncthreads();

    const int r = tid >> 2, c = tid & 3;
    float sum = 0.0f;
#pragma unroll
    for (int sp = 0; sp < 8; sp++) sum += pbuf[(size_t)(sp * BM + r) * NCOL + c];
    sum += __ldg(&bias[c]);
    out[(size_t)(row0 + r) * NCOL + c] = sum;
}

// Diagnostic no-ops: shift ncu's fixed -s 5 capture window onto pass1_mma.
__global__ void dummy_a() {}
__global__ void dummy_b() {}

// ---------------- launch ----------------
extern "C" void kernel_launch(void* const* d_in, const int* in_sizes, int n_in,
                              void* d_out, int out_size) {
    const float* A  = (const float*)d_in[0];
    const float* X  = (const float*)d_in[1];
    const float* W1 = (const float*)d_in[2];
    const float* b1 = (const float*)d_in[3];
    const float* W2 = (const float*)d_in[4];
    const float* b2 = (const float*)d_in[5];
    float* out = (float*)d_out;

    float *wtp, *hw2p;
    cudaGetSymbolAddress((void**)&wtp, g_WT);
    cudaGetSymbolAddress((void**)&hw2p, g_HW2);

    // 0) WT = tf32-split (X @ W1)^T
    xw1t_kernel<<<NROWS / 32, 256>>>(X, W1, wtp);

    // 1) HW2 = relu(A @ XW1 + b1) @ W2   (mma.sync 3xTF32)
    constexpr int SMEM_P1 = 2 * (64 * 132 + 2 * 16 * 132) * 4;   // 101376 B
    cudaFuncSetAttribute(pass1_mma, cudaFuncAttributeMaxDynamicSharedMemorySize, SMEM_P1);
    pass1_mma<<<NROWS / 64, 256, SMEM_P1>>>(A, wtp, b1, W2, hw2p);

    // 2) logits = A @ HW2 + b2           (SIMT, memory-bound)
    constexpr int SMEM_P2 = (2 * 64 * 132 + 2 * 128 * 4) * 4;    // 71680 B
    cudaFuncSetAttribute(pass2_kernel, cudaFuncAttributeMaxDynamicSharedMemorySize, SMEM_P2);
    pass2_kernel<<<NROWS / 64, 256, SMEM_P2>>>(A, hw2p, b2, out);

    dummy_a<<<1, 32>>>();
    dummy_b<<<1, 32>>>();
}

// round 9
// speedup vs baseline: 2.1427x; 1.0216x over previous
#include <cuda_runtime.h>
#include <cstdint>
#include <cstddef>

#define NROWS 16384
#define DIN 128
#define DH 16
#define DOUT 4

typedef unsigned long long u64;
typedef unsigned int u32;

// Scratch (device globals: allocations are forbidden)
__device__ float g_WT[2 * DH * NROWS]; // rows 0-15: tf32_hi((X@W1)^T), rows 16-31: tf32_lo
__device__ float g_HW2[NROWS * DOUT];  // relu(...) @ W2  [16384,4]

// ---------------- PTX helpers ----------------
__device__ __forceinline__ void cp_async16(void* smem_ptr, const void* gmem_ptr) {
    unsigned saddr = (unsigned)__cvta_generic_to_shared(smem_ptr);
    asm volatile("cp.async.cg.shared.global [%0], [%1], 16;\n" :: "r"(saddr), "l"(gmem_ptr));
}
__device__ __forceinline__ void cp_commit() { asm volatile("cp.async.commit_group;\n"); }
template <int N>
__device__ __forceinline__ void cp_wait() { asm volatile("cp.async.wait_group %0;\n" :: "n"(N)); }

__device__ __forceinline__ u64 dup2(float a) {
    u64 r; asm("mov.b64 %0, {%1, %1};" : "=l"(r) : "f"(a)); return r;
}
__device__ __forceinline__ void fma2(u64& acc, u64 a, u64 b) {
    asm("fma.rn.f32x2 %0, %1, %2, %0;" : "+l"(acc) : "l"(a), "l"(b));
}
__device__ __forceinline__ u32 cvt_tf32(float x) {
    u32 r; asm("cvt.rna.tf32.f32 %0, %1;" : "=r"(r) : "f"(x)); return r;
}
// m16n8k8 tf32 HMMA (base sm_80+ ISA, valid on non-'a' sm_103 target)
__device__ __forceinline__ void mma_tf32(float4& d, u32 a0, u32 a1, u32 a2, u32 a3,
                                         u32 b0, u32 b1) {
    asm volatile("mma.sync.aligned.m16n8k8.row.col.f32.tf32.tf32.f32 "
                 "{%0,%1,%2,%3}, {%4,%5,%6,%7}, {%8,%9}, {%0,%1,%2,%3};"
                 : "+f"(d.x), "+f"(d.y), "+f"(d.z), "+f"(d.w)
                 : "r"(a0), "r"(a1), "r"(a2), "r"(a3), "r"(b0), "r"(b1));
}

// Diagnostic no-ops: ncu empirically profiles launch index 3 -> land it on pass1_mma.
__global__ void dummy_a() {}
__global__ void dummy_b() {}

// ---------------- Kernel 0: WT_hi/lo = tf32-split of (X @ W1)^T ----------------
__global__ __launch_bounds__(256)
void xw1t_kernel(const float* __restrict__ X, const float* __restrict__ W1,
                 float* __restrict__ WT) {
    __shared__ float xs[32 * DIN];
    __shared__ float w1s[DIN * DH];
    const int tid = threadIdx.x;
    for (int i = tid; i < DIN * DH / 2; i += 256)
        ((float2*)w1s)[i] = ((const float2*)W1)[i];
    const float4* xg = (const float4*)(X + (size_t)blockIdx.x * 32 * DIN);
#pragma unroll
    for (int t = 0; t < 4; t++)
        ((float4*)xs)[t * 256 + tid] = xg[t * 256 + tid];
    __syncthreads();
#pragma unroll
    for (int t = 0; t < 2; t++) {
        int i = t * 256 + tid;
        int r = i >> 4, c = i & 15;
        float acc = 0.0f;
#pragma unroll
        for (int k = 0; k < DIN; k++) acc += xs[r * DIN + k] * w1s[k * DH + c];
        u32 hi = cvt_tf32(acc);
        float lo = acc - __uint_as_float(hi);
        size_t col = (size_t)blockIdx.x * 32 + r;
        WT[(size_t)c * NROWS + col]        = __uint_as_float(hi);
        WT[(size_t)(DH + c) * NROWS + col] = __uint_as_float(cvt_tf32(lo));
    }
}

// ---------------- Pass 1 (HMMA 3xTF32, BM=128): HW2 = relu(A @ XW1 + b1) @ W2 ----------------
// 8 warps = pure k-split; each warp computes all 8 m16-tiles x 2 n8-tiles.
// BM=128 halves B-operand (WT) L2 traffic vs BM=64.
__global__ __launch_bounds__(256, 1)
void pass1_mma(const float* __restrict__ A, const float* __restrict__ WT,
               const float* __restrict__ b1, const float* __restrict__ W2,
               float* __restrict__ out) {
    constexpr int BM = 128, BK = 128;
    constexpr int STRIDE = 132;
    constexpr int NST = NROWS / BK;           // 128
    constexpr int ABUF = BM * STRIDE;         // 16896 floats
    constexpr int WBUF = DH * STRIDE;         // 2112 floats (hi or lo block)
    constexpr int SB = ABUF + 2 * WBUF;       // 21120 floats per stage

    extern __shared__ float fsm[];
    const int tid  = threadIdx.x;
    const int w    = tid >> 5;                // ksplit 0..7
    const int lane = tid & 31;
    const int gid  = lane >> 2;               // 0..7
    const int tig  = lane & 3;                // 0..3
    const int row0 = blockIdx.x * BM;

    auto load_stage = [&](int s) {
        float* base = fsm + (s & 1) * SB;
        const size_t kb = (size_t)s * BK;
#pragma unroll
        for (int t = 0; t < 16; t++) {         // A: 128x128 = 4096 float4
            int idx = t * 256 + tid;
            int r = idx >> 5, c4 = idx & 31;
            cp_async16(base + r * STRIDE + c4 * 4,
                       A + (size_t)(row0 + r) * NROWS + kb + c4 * 4);
        }
#pragma unroll
        for (int t = 0; t < 4; t++) {          // WT hi+lo: 32 rows x 32 chunks
            int idx = t * 256 + tid;
            int r = idx >> 5, c4 = idx & 31;
            cp_async16(base + ABUF + r * STRIDE + c4 * 4,
                       WT + (size_t)r * NROWS + kb + c4 * 4);
        }
        cp_commit();
    };

    load_stage(0);
    load_stage(1);

    float4 C[8][2];                            // [mtile][ntile]
#pragma unroll
    for (int m = 0; m < 8; m++)
#pragma unroll
        for (int n = 0; n < 2; n++) C[m][n] = make_float4(0.f, 0.f, 0.f, 0.f);

    for (int s = 0; s < NST; s++) {
        if (s + 1 < NST) cp_wait<1>(); else cp_wait<0>();
        __syncthreads();
        const float* base = fsm + (s & 1) * SB;
        const int k0 = w * 16;
#pragma unroll
        for (int k8 = 0; k8 < 2; k8++) {
            const float* bh = base + ABUF + gid * STRIDE + k0 + k8 * 8 + tig;
            const float* bl = bh + DH * STRIDE;
            u32 bh00 = __float_as_uint(bh[0]);
            u32 bh01 = __float_as_uint(bh[4]);
            u32 bh10 = __float_as_uint(bh[8 * STRIDE]);
            u32 bh11 = __float_as_uint(bh[8 * STRIDE + 4]);
            u32 bl00 = __float_as_uint(bl[0]);
            u32 bl01 = __float_as_uint(bl[4]);
            u32 bl10 = __float_as_uint(bl[8 * STRIDE]);
            u32 bl11 = __float_as_uint(bl[8 * STRIDE + 4]);
#pragma unroll
            for (int mt = 0; mt < 8; mt++) {
                const float* ap = base + (mt * 16 + gid) * STRIDE + k0 + k8 * 8 + tig;
                float av0 = ap[0], av1 = ap[8 * STRIDE], av2 = ap[4], av3 = ap[8 * STRIDE + 4];
                u32 ah0 = cvt_tf32(av0), ah1 = cvt_tf32(av1);
                u32 ah2 = cvt_tf32(av2), ah3 = cvt_tf32(av3);
                u32 al0 = cvt_tf32(av0 - __uint_as_float(ah0));
                u32 al1 = cvt_tf32(av1 - __uint_as_float(ah1));
                u32 al2 = cvt_tf32(av2 - __uint_as_float(ah2));
                u32 al3 = cvt_tf32(av3 - __uint_as_float(ah3));
                mma_tf32(C[mt][0], ah0, ah1, ah2, ah3, bh00, bh01);
                mma_tf32(C[mt][0], al0, al1, al2, al3, bh00, bh01);
                mma_tf32(C[mt][0], ah0, ah1, ah2, ah3, bl00, bl01);
                mma_tf32(C[mt][1], ah0, ah1, ah2, ah3, bh10, bh11);
                mma_tf32(C[mt][1], al0, al1, al2, al3, bh10, bh11);
                mma_tf32(C[mt][1], ah0, ah1, ah2, ah3, bl10, bl11);
            }
        }
        __syncthreads();
        if (s + 2 < NST) load_stage(s + 2);
    }

    // ---- epilogue: reduce 8 ksplit partials, bias+relu, fuse H@W2 ----
    float* psum = fsm;                         // [8][128][16] = 64 KB
    {
        float* p = psum + w * (BM * DH);
#pragma unroll
        for (int mt = 0; mt < 8; mt++) {
            const int rb = mt * 16 + gid;
            *(float2*)(p + rb * DH + 2 * tig)           = make_float2(C[mt][0].x, C[mt][0].y);
            *(float2*)(p + (rb + 8) * DH + 2 * tig)     = make_float2(C[mt][0].z, C[mt][0].w);
            *(float2*)(p + rb * DH + 8 + 2 * tig)       = make_float2(C[mt][1].x, C[mt][1].y);
            *(float2*)(p + (rb + 8) * DH + 8 + 2 * tig) = make_float2(C[mt][1].z, C[mt][1].w);
        }
    }
    __syncthreads();
    float* hbuf = fsm + 8 * BM * DH;           // [128][16] right after psum
#pragma unroll
    for (int t = 0; t < 8; t++) {
        int i = t * 256 + tid;                 // 2048 h values
        float sum = 0.0f;
#pragma unroll
        for (int sp = 0; sp < 8; sp++) sum += psum[sp * (BM * DH) + i];
        sum += __ldg(&b1[i & 15]);
        hbuf[i] = fmaxf(sum, 0.0f);
    }
    __syncthreads();
#pragma unroll
    for (int t = 0; t < 2; t++) {
        int i = t * 256 + tid;                 // 512 outputs
        const int r = i >> 2, c = i & 3;
        float o = 0.0f;
#pragma unroll
        for (int j = 0; j < DH; j++)
            o += hbuf[r * DH + j] * __ldg(&W2[j * DOUT + c]);
        out[(size_t)(row0 + r) * DOUT + c] = o;
    }
}

// ---------------- Pass 2 (SIMT, memory-bound): logits = A @ HW2 + b2 ----------------
__global__ __launch_bounds__(256, 2)
void pass2_kernel(const float* __restrict__ A, const float* __restrict__ W,
                  const float* __restrict__ bias, float* __restrict__ out) {
    constexpr int NCOL = 4;
    constexpr int BM = 64, BK = 128;
    constexpr int STRIDE = 132;
    constexpr int NST = NROWS / BK;
    constexpr int ABUF = BM * STRIDE;
    constexpr int WBUF = BK * NCOL;

    extern __shared__ float fsm[];
    float* As[2] = { fsm, fsm + ABUF };
    float* Ws[2] = { fsm + 2 * ABUF, fsm + 2 * ABUF + WBUF };

    const int tid  = threadIdx.x;
    const int w    = tid >> 5;                // ksplit 0..7 (16 k's)
    const int lane = tid & 31;
    const int row0 = blockIdx.x * BM;

    auto load_stage = [&](int s) {
        const int buf = s & 1;
        const size_t kbase = (size_t)s * BK;
#pragma unroll
        for (int t = 0; t < 8; t++) {
            int idx = t * 256 + tid;
            int r = idx >> 5, c4 = idx & 31;
            cp_async16(As[buf] + r * STRIDE + c4 * 4,
                       A + (size_t)(row0 + r) * NROWS + kbase + c4 * 4);
        }
        if (tid < WBUF / 4)
            cp_async16(Ws[buf] + tid * 4, W + kbase * NCOL + tid * 4);
        cp_commit();
    };

    load_stage(0);
    load_stage(1);

    u64 acc[2][2] = {{0ull, 0ull}, {0ull, 0ull}};   // [rowhalf][colpair]

    for (int s = 0; s < NST; s++) {
        if (s + 1 < NST) cp_wait<1>(); else cp_wait<0>();
        __syncthreads();
        const int buf = s & 1;
        const float* ab = As[buf] + lane * STRIDE + w * 16;
        const float* wp = Ws[buf] + w * 16 * NCOL;
#pragma unroll
        for (int kh = 0; kh < 4; kh++) {
            float4 a0 = *(const float4*)(ab + kh * 4);
            float4 a1 = *(const float4*)(ab + 32 * STRIDE + kh * 4);
#pragma unroll
            for (int k2 = 0; k2 < 4; k2++) {
                const int k = kh * 4 + k2;
                ulonglong2 wv = *(const ulonglong2*)(wp + k * NCOL);  // warp-uniform
                u64 d0 = dup2(((const float*)&a0)[k2]);
                u64 d1 = dup2(((const float*)&a1)[k2]);
                fma2(acc[0][0], d0, wv.x);
                fma2(acc[0][1], d0, wv.y);
                fma2(acc[1][0], d1, wv.x);
                fma2(acc[1][1], d1, wv.y);
            }
        }
        __syncthreads();
        if (s + 2 < NST) load_stage(s + 2);
    }

    float* pbuf = fsm;                         // [8][64][4] = 8 KB
#pragma unroll
    for (int rh = 0; rh < 2; rh++)
        *(float4*)(pbuf + (size_t)(w * BM + lane + rh * 32) * NCOL) =
            make_float4(__uint_as_float((u32)acc[rh][0]),
                        __uint_as_float((u32)(acc[rh][0] >> 32)),
                        __uint_as_float((u32)acc[rh][1]),
                        __uint_as_float((u32)(acc[rh][1] >> 32)));
    __syncthreads();

    const int r = tid >> 2, c = tid & 3;
    float sum = 0.0f;
#pragma unroll
    for (int sp = 0; sp < 8; sp++) sum += pbuf[(size_t)(sp * BM + r) * NCOL + c];
    sum += __ldg(&bias[c]);
    out[(size_t)(row0 + r) * NCOL + c] = sum;
}

// ---------------- launch ----------------
extern "C" void kernel_launch(void* const* d_in, const int* in_sizes, int n_in,
                              void* d_out, int out_size) {
    const float* A  = (const float*)d_in[0];
    const float* X  = (const float*)d_in[1];
    const float* W1 = (const float*)d_in[2];
    const float* b1 = (const float*)d_in[3];
    const float* W2 = (const float*)d_in[4];
    const float* b2 = (const float*)d_in[5];
    float* out = (float*)d_out;

    float *wtp, *hw2p;
    cudaGetSymbolAddress((void**)&wtp, g_WT);
    cudaGetSymbolAddress((void**)&hw2p, g_HW2);

    // #0, #1: no-ops so ncu's captured launch (index 3) is pass1_mma
    dummy_a<<<1, 32>>>();
    dummy_b<<<1, 32>>>();

    // #2) WT = tf32-split (X @ W1)^T
    xw1t_kernel<<<NROWS / 32, 256>>>(X, W1, wtp);

    // #3) HW2 = relu(A @ XW1 + b1) @ W2   (mma.sync 3xTF32, BM=128)
    constexpr int SMEM_P1 = 2 * (128 * 132 + 2 * 16 * 132) * 4;   // 168960 B
    cudaFuncSetAttribute(pass1_mma, cudaFuncAttributeMaxDynamicSharedMemorySize, SMEM_P1);
    pass1_mma<<<NROWS / 128, 256, SMEM_P1>>>(A, wtp, b1, W2, hw2p);

    // #4) logits = A @ HW2 + b2           (SIMT, memory-bound)
    constexpr int SMEM_P2 = (2 * 64 * 132 + 2 * 128 * 4) * 4;     // 71680 B
    cudaFuncSetAttribute(pass2_kernel, cudaFuncAttributeMaxDynamicSharedMemorySize, SMEM_P2);
    pass2_kernel<<<NROWS / 64, 256, SMEM_P2>>>(A, hw2p, b2, out);
}